// round 2
// baseline (speedup 1.0000x reference)
#include <cuda_runtime.h>
#include <cstdint>

#define D_MODEL  1024
#define N_CTX    2049
#define B_SZ     2
#define SEQ_LEN  2048
#define M_ROWS   (B_SZ * N_CTX)   /* 4098 */
#define N_HEADS  16
#define D_K      64
#define N_LAYERS 16
#define VOCAB    256

typedef unsigned long long ull;

// ---------------- device scratch (allocation-free rule: __device__ globals) ----------------
__device__ float g_X[M_ROWS * D_MODEL];
__device__ float g_Q[M_ROWS * D_MODEL];
__device__ float g_K[M_ROWS * D_MODEL];
__device__ float g_V[M_ROWS * D_MODEL];
__device__ float g_O[M_ROWS * D_MODEL];

// ---------------- packed f32x2 helpers (sm_103a FFMA2 path) ----------------
__device__ __forceinline__ ull pack2(float x, float y) {
    ull r; asm("mov.b64 %0, {%1, %2};" : "=l"(r) : "f"(x), "f"(y)); return r;
}
__device__ __forceinline__ void fma2(ull& d, ull a, ull b) {
    asm("fma.rn.f32x2 %0, %1, %2, %3;" : "=l"(d) : "l"(a), "l"(b), "l"(d));
}
__device__ __forceinline__ ull mul2(ull a, ull b) {
    ull r; asm("mul.rn.f32x2 %0, %1, %2;" : "=l"(r) : "l"(a), "l"(b)); return r;
}
__device__ __forceinline__ float2 unpack2(ull v) {
    float2 r; asm("mov.b64 {%0, %1}, %2;" : "=f"(r.x), "=f"(r.y) : "l"(v)); return r;
}

// ---------------- embedding (with bos prepend) ----------------
__global__ void embed_kernel(const int* __restrict__ ids, const float* __restrict__ emb) {
    int i = blockIdx.x * blockDim.x + threadIdx.x;
    if (i >= M_ROWS * D_MODEL) return;
    int r = i >> 10;
    int d = i & 1023;
    int b = r / N_CTX;
    int t = r - b * N_CTX;
    int tok = (t == 0) ? 0 : ids[b * SEQ_LEN + (t - 1)];
    g_X[i] = emb[tok * D_MODEL + d];
}

// ---------------- SGEMM: C[M,1024] = A[M,1024] @ Bw[1024,1024] (+ Res) ----------------
// 128x128x16 tile, 256 threads, 8x8 microtile, f32x2 accumulators, double-buffered smem.
__global__ __launch_bounds__(256, 2) void sgemm1024(const float* __restrict__ A,
                                                    const float* __restrict__ Bw,
                                                    const float* __restrict__ Res,
                                                    float* __restrict__ C) {
    __shared__ float As[2][16][128];
    __shared__ float Bs[2][16][128];
    const int tid = threadIdx.x;
    const int tx = tid & 15;
    const int ty = tid >> 4;
    const int row0 = blockIdx.y * 128;
    const int col0 = blockIdx.x * 128;

    // load-index precompute
    const int aM0 = tid >> 2,          aK0 = (tid & 3) << 2;
    const int aM1 = (tid + 256) >> 2,  aK1 = ((tid + 256) & 3) << 2;
    const int bK0 = tid >> 5,          bN0 = (tid & 31) << 2;
    const int bK1 = (tid + 256) >> 5,  bN1 = ((tid + 256) & 31) << 2;
    const int agr0 = row0 + aM0, agr1 = row0 + aM1;

    ull c2[8][4];
    #pragma unroll
    for (int i = 0; i < 8; i++)
        #pragma unroll
        for (int j = 0; j < 4; j++) c2[i][j] = 0ULL;

    float4 ra0, ra1, rb0, rb1;
    // prefetch k0 = 0
    {
        ra0 = make_float4(0.f, 0.f, 0.f, 0.f);
        ra1 = make_float4(0.f, 0.f, 0.f, 0.f);
        if (agr0 < M_ROWS) ra0 = *(const float4*)&A[(size_t)agr0 * 1024 + aK0];
        if (agr1 < M_ROWS) ra1 = *(const float4*)&A[(size_t)agr1 * 1024 + aK1];
        rb0 = *(const float4*)&Bw[(size_t)bK0 * 1024 + col0 + bN0];
        rb1 = *(const float4*)&Bw[(size_t)bK1 * 1024 + col0 + bN1];
        As[0][aK0 + 0][aM0] = ra0.x; As[0][aK0 + 1][aM0] = ra0.y;
        As[0][aK0 + 2][aM0] = ra0.z; As[0][aK0 + 3][aM0] = ra0.w;
        As[0][aK1 + 0][aM1] = ra1.x; As[0][aK1 + 1][aM1] = ra1.y;
        As[0][aK1 + 2][aM1] = ra1.z; As[0][aK1 + 3][aM1] = ra1.w;
        *(float4*)&Bs[0][bK0][bN0] = rb0;
        *(float4*)&Bs[0][bK1][bN1] = rb1;
    }
    __syncthreads();

    for (int kt = 0; kt < 64; kt++) {
        const int cur = kt & 1;
        const int nxt = cur ^ 1;
        if (kt < 63) {
            const int k0 = (kt + 1) * 16;
            ra0 = make_float4(0.f, 0.f, 0.f, 0.f);
            ra1 = make_float4(0.f, 0.f, 0.f, 0.f);
            if (agr0 < M_ROWS) ra0 = *(const float4*)&A[(size_t)agr0 * 1024 + k0 + aK0];
            if (agr1 < M_ROWS) ra1 = *(const float4*)&A[(size_t)agr1 * 1024 + k0 + aK1];
            rb0 = *(const float4*)&Bw[(size_t)(k0 + bK0) * 1024 + col0 + bN0];
            rb1 = *(const float4*)&Bw[(size_t)(k0 + bK1) * 1024 + col0 + bN1];
        }
        #pragma unroll
        for (int kk = 0; kk < 16; kk++) {
            float4 a0 = *(const float4*)&As[cur][kk][ty * 8];
            float4 a1 = *(const float4*)&As[cur][kk][ty * 8 + 4];
            const ull* bu = (const ull*)&Bs[cur][kk][tx * 8];
            ull b0 = bu[0], b1 = bu[1], b2v = bu[2], b3 = bu[3];
            float av[8] = {a0.x, a0.y, a0.z, a0.w, a1.x, a1.y, a1.z, a1.w};
            #pragma unroll
            for (int i = 0; i < 8; i++) {
                ull ad = pack2(av[i], av[i]);
                fma2(c2[i][0], ad, b0);
                fma2(c2[i][1], ad, b1);
                fma2(c2[i][2], ad, b2v);
                fma2(c2[i][3], ad, b3);
            }
        }
        if (kt < 63) {
            As[nxt][aK0 + 0][aM0] = ra0.x; As[nxt][aK0 + 1][aM0] = ra0.y;
            As[nxt][aK0 + 2][aM0] = ra0.z; As[nxt][aK0 + 3][aM0] = ra0.w;
            As[nxt][aK1 + 0][aM1] = ra1.x; As[nxt][aK1 + 1][aM1] = ra1.y;
            As[nxt][aK1 + 2][aM1] = ra1.z; As[nxt][aK1 + 3][aM1] = ra1.w;
            *(float4*)&Bs[nxt][bK0][bN0] = rb0;
            *(float4*)&Bs[nxt][bK1][bN1] = rb1;
            __syncthreads();
        }
    }

    // epilogue
    #pragma unroll
    for (int i = 0; i < 8; i++) {
        int gr = row0 + ty * 8 + i;
        if (gr >= M_ROWS) continue;
        #pragma unroll
        for (int j = 0; j < 4; j++) {
            float2 cc = unpack2(c2[i][j]);
            int col = col0 + tx * 8 + j * 2;
            if (Res) {
                float2 r = *(const float2*)&Res[(size_t)gr * 1024 + col];
                cc.x += r.x; cc.y += r.y;
            }
            *(float2*)&C[(size_t)gr * 1024 + col] = cc;
        }
    }
}

// ---------------- causal flash attention (fp32 f32x2, one thread per query) ----------------
#define AKT 16
__global__ __launch_bounds__(256) void attn_kernel(const float* __restrict__ Qm,
                                                   const float* __restrict__ Km,
                                                   const float* __restrict__ Vm,
                                                   float* __restrict__ Om) {
    const int h = blockIdx.y;
    const int b = blockIdx.z;
    int q0 = blockIdx.x * 256;
    if (q0 + 256 > N_CTX) q0 = N_CTX - 256;   // clamp last tile (overlap recomputes identical values)
    const int q = q0 + threadIdx.x;
    const size_t base = (size_t)b * N_CTX * D_MODEL + h * D_K;

    __shared__ float Ks[AKT][64];
    __shared__ float Vs[AKT][64];

    ull q2[32];
    {
        const ulonglong2* qp = (const ulonglong2*)(Qm + base + (size_t)q * D_MODEL);
        #pragma unroll
        for (int i = 0; i < 16; i++) {
            ulonglong2 t = qp[i];
            q2[2 * i] = t.x; q2[2 * i + 1] = t.y;
        }
    }
    ull o2[32];
    #pragma unroll
    for (int d = 0; d < 32; d++) o2[d] = 0ULL;
    float mrun = -1e30f, lrun = 0.f;

    const int kmax = q0 + 256;
    for (int k0 = 0; k0 < kmax; k0 += AKT) {
        __syncthreads();
        {
            int idx = threadIdx.x;               // AKT*64/4 == 256 float4 loads
            int kk = idx >> 4;
            int c4 = (idx & 15) << 2;
            int kg = k0 + kk;
            float4 kv = make_float4(0.f, 0.f, 0.f, 0.f);
            float4 vv = make_float4(0.f, 0.f, 0.f, 0.f);
            if (kg < N_CTX) {
                kv = *(const float4*)(Km + base + (size_t)kg * D_MODEL + c4);
                vv = *(const float4*)(Vm + base + (size_t)kg * D_MODEL + c4);
            }
            *(float4*)&Ks[kk][c4] = kv;
            *(float4*)&Vs[kk][c4] = vv;
        }
        __syncthreads();
        if (k0 <= q) {
            float s[AKT];
            float tmax = -1e30f;
            #pragma unroll
            for (int j = 0; j < AKT; j++) {
                ull a0 = 0ULL, a1 = 0ULL, a2 = 0ULL, a3 = 0ULL;
                const ulonglong2* kp = (const ulonglong2*)&Ks[j][0];
                #pragma unroll
                for (int dd = 0; dd < 16; dd += 2) {
                    ulonglong2 k4 = kp[dd];
                    fma2(a0, q2[2 * dd],     k4.x);
                    fma2(a1, q2[2 * dd + 1], k4.y);
                    ulonglong2 k5 = kp[dd + 1];
                    fma2(a2, q2[2 * dd + 2], k5.x);
                    fma2(a3, q2[2 * dd + 3], k5.y);
                }
                float2 u0 = unpack2(a0), u1 = unpack2(a1);
                float2 u2 = unpack2(a2), u3 = unpack2(a3);
                float sv = (((u0.x + u0.y) + (u1.x + u1.y)) +
                            ((u2.x + u2.y) + (u3.x + u3.y))) * 0.125f;
                sv = (k0 + j <= q) ? sv : -1e30f;
                s[j] = sv;
                tmax = fmaxf(tmax, sv);
            }
            float mn = fmaxf(mrun, tmax);
            if (mn > mrun) {
                float corr = __expf(mrun - mn);
                lrun *= corr;
                ull cp = pack2(corr, corr);
                #pragma unroll
                for (int d = 0; d < 32; d++) o2[d] = mul2(o2[d], cp);
                mrun = mn;
            }
            #pragma unroll
            for (int j = 0; j < AKT; j++) {
                float p = __expf(s[j] - mrun);
                lrun += p;
                ull pp = pack2(p, p);
                const ulonglong2* vp = (const ulonglong2*)&Vs[j][0];
                #pragma unroll
                for (int dd = 0; dd < 16; dd++) {
                    ulonglong2 v4 = vp[dd];
                    fma2(o2[2 * dd],     pp, v4.x);
                    fma2(o2[2 * dd + 1], pp, v4.y);
                }
            }
        }
    }
    {
        const float inv = 1.f / lrun;
        ull ip = pack2(inv, inv);
        ulonglong2* op = (ulonglong2*)(Om + base + (size_t)q * D_MODEL);
        #pragma unroll
        for (int i = 0; i < 16; i++) {
            ulonglong2 t;
            t.x = mul2(o2[2 * i], ip);
            t.y = mul2(o2[2 * i + 1], ip);
            op[i] = t;
        }
    }
}

// ---------------- fused logits + softmax into d_out slice l (f32x2 GEMV) ----------------
__global__ __launch_bounds__(256) void probs_kernel(const float* __restrict__ X,
                                                    const float* __restrict__ Wout,
                                                    float* __restrict__ out,
                                                    int l) {
    // rows stored pair-interleaved: xs2[p][k] = (X[row0+2p][k], X[row0+2p+1][k])
    __shared__ ull xs2[4][1024];            // 32 KB
    __shared__ float red[8][8];
    const int tid = threadIdx.x;
    const int row0 = blockIdx.x * 8;

    #pragma unroll
    for (int it = 0; it < 8; it++) {
        int idx = tid + it * 256;           // 0..2047 float4 loads
        int m = idx >> 8;                   // 0..7
        int c4 = idx & 255;
        int gr = row0 + m;
        float4 v = make_float4(0.f, 0.f, 0.f, 0.f);
        if (gr < M_ROWS) v = ((const float4*)&X[(size_t)gr * 1024])[c4];
        float* dst = (float*)&xs2[m >> 1][0];
        int e = m & 1;
        dst[(c4 * 4 + 0) * 2 + e] = v.x;
        dst[(c4 * 4 + 1) * 2 + e] = v.y;
        dst[(c4 * 4 + 2) * 2 + e] = v.z;
        dst[(c4 * 4 + 3) * 2 + e] = v.w;
    }
    __syncthreads();

    ull acce[4], acco[4];
    #pragma unroll
    for (int p = 0; p < 4; p++) { acce[p] = 0ULL; acco[p] = 0ULL; }
    const int v = tid;
    #pragma unroll 2
    for (int k = 0; k < 1024; k += 2) {
        float w0 = Wout[k * VOCAB + v];
        float w1 = Wout[(k + 1) * VOCAB + v];
        ull wp0 = pack2(w0, w0);
        ull wp1 = pack2(w1, w1);
        #pragma unroll
        for (int p = 0; p < 4; p++) {
            ulonglong2 x = *(const ulonglong2*)&xs2[p][k];
            fma2(acce[p], x.x, wp0);
            fma2(acco[p], x.y, wp1);
        }
    }
    float acc[8];
    #pragma unroll
    for (int p = 0; p < 4; p++) {
        float2 e = unpack2(acce[p]);
        float2 o = unpack2(acco[p]);
        acc[2 * p] = e.x + o.x;
        acc[2 * p + 1] = e.y + o.y;
    }

    const int lane = tid & 31;
    const int wid  = tid >> 5;
    float bmax[8];
    #pragma unroll
    for (int m = 0; m < 8; m++) {
        float x = acc[m];
        #pragma unroll
        for (int off = 16; off; off >>= 1)
            x = fmaxf(x, __shfl_xor_sync(0xffffffffu, x, off));
        if (lane == 0) red[m][wid] = x;
    }
    __syncthreads();
    #pragma unroll
    for (int m = 0; m < 8; m++) {
        float mx = red[m][0];
        #pragma unroll
        for (int w = 1; w < 8; w++) mx = fmaxf(mx, red[m][w]);
        bmax[m] = mx;
    }
    __syncthreads();
    float p[8];
    #pragma unroll
    for (int m = 0; m < 8; m++) {
        p[m] = __expf(acc[m] - bmax[m]);
        float x = p[m];
        #pragma unroll
        for (int off = 16; off; off >>= 1)
            x += __shfl_xor_sync(0xffffffffu, x, off);
        if (lane == 0) red[m][wid] = x;
    }
    __syncthreads();
    #pragma unroll
    for (int m = 0; m < 8; m++) {
        float sm = 0.f;
        #pragma unroll
        for (int w = 0; w < 8; w++) sm += red[m][w];
        int gr = row0 + m;
        if (gr < M_ROWS) {
            int b = gr / N_CTX;
            int t = gr - b * N_CTX;
            out[(((size_t)l * B_SZ + b) * N_CTX + t) * VOCAB + v] = p[m] / sm;
        }
    }
}

// ---------------- orchestration ----------------
extern "C" void kernel_launch(void* const* d_in, const int* in_sizes, int n_in,
                              void* d_out, int out_size) {
    const int*   ids  = (const int*)d_in[0];
    const float* emb  = (const float*)d_in[1];
    const float* Wq   = (const float*)d_in[2];
    const float* Wk   = (const float*)d_in[3];
    const float* Wv   = (const float*)d_in[4];
    const float* Wo   = (const float*)d_in[5];
    const float* Wout = (const float*)d_in[6];
    float* out = (float*)d_out;

    float *X, *Q, *K, *V, *O;
    cudaGetSymbolAddress((void**)&X, g_X);
    cudaGetSymbolAddress((void**)&Q, g_Q);
    cudaGetSymbolAddress((void**)&K, g_K);
    cudaGetSymbolAddress((void**)&V, g_V);
    cudaGetSymbolAddress((void**)&O, g_O);

    embed_kernel<<<(M_ROWS * D_MODEL + 255) / 256, 256>>>(ids, emb);
    probs_kernel<<<(M_ROWS + 7) / 8, 256>>>(X, Wout, out, 0);

    dim3 ggrid(8, (M_ROWS + 127) / 128);
    dim3 agrid((N_CTX + 255) / 256, N_HEADS, B_SZ);
    for (int l = 0; l < N_LAYERS; l++) {
        const float* wq = Wq + (size_t)l * D_MODEL * D_MODEL;
        const float* wk = Wk + (size_t)l * D_MODEL * D_MODEL;
        const float* wv = Wv + (size_t)l * D_MODEL * D_MODEL;
        const float* wo = Wo + (size_t)l * D_MODEL * D_MODEL;
        sgemm1024<<<ggrid, 256>>>(X, wq, nullptr, Q);
        sgemm1024<<<ggrid, 256>>>(X, wk, nullptr, K);
        sgemm1024<<<ggrid, 256>>>(X, wv, nullptr, V);
        attn_kernel<<<agrid, 256>>>(Q, K, V, O);
        sgemm1024<<<ggrid, 256>>>(O, wo, X, X);   // X = X + O @ Wo
        probs_kernel<<<(M_ROWS + 7) / 8, 256>>>(X, Wout, out, l + 1);
    }
}